// round 4
// baseline (speedup 1.0000x reference)
#include <cuda_runtime.h>
#include <cstdint>

// ---------------------------------------------------------------------------
// Scratch: FPS index buffer (max level-1 size: 8 batches x 4096 points)
// ---------------------------------------------------------------------------
__device__ int g_fps_idx[8 * 4096];

typedef unsigned long long u64;

// ---------------------------------------------------------------------------
// Cluster helpers
// ---------------------------------------------------------------------------
__device__ __forceinline__ uint32_t smem_u32(const void* p) {
    uint32_t a;
    asm("{ .reg .u64 t; cvta.to.shared.u64 t, %1; cvt.u32.u64 %0, t; }"
        : "=r"(a) : "l"(p));
    return a;
}
__device__ __forceinline__ uint32_t mapa_rank(uint32_t addr, uint32_t rank) {
    uint32_t o;
    asm("mapa.shared::cluster.u32 %0, %1, %2;" : "=r"(o) : "r"(addr), "r"(rank));
    return o;
}
__device__ __forceinline__ uint32_t my_cluster_rank() {
    uint32_t r; asm("mov.u32 %0, %%cluster_ctarank;" : "=r"(r)); return r;
}
__device__ __forceinline__ void mbar_wait_cluster(uint32_t addr, uint32_t parity) {
    asm volatile(
        "{\n\t"
        ".reg .pred P;\n\t"
        "WL%=:\n\t"
        "mbarrier.try_wait.parity.acquire.cluster.shared::cta.b64 P, [%0], %1;\n\t"
        "@!P bra WL%=;\n\t"
        "}"
        :: "r"(addr), "r"(parity) : "memory");
}

// ---------------------------------------------------------------------------
// Level-1 FPS across a 4-CTA cluster. N=8192, npoints=4096.
// Each CTA owns 2048 points (K=2 register-resident distances) but holds a
// FULL float4 copy of all 8192 coords in SMEM, so only the 8-byte winner key
// crosses the cluster fabric each iteration.
// Distance math is VERBATIM from the R3 kernel (bit-matched to reference).
// Key packing: (valbits<<32) | (0xFFFFFFFF - idx) -> u64 max == max value,
// min index among ties (exact jnp.argmax first-occurrence).
// ---------------------------------------------------------------------------
__global__ void __cluster_dims__(4, 1, 1) __launch_bounds__(1024, 1)
fps1_cluster(const float* __restrict__ pts, int* __restrict__ idx_out)
{
    constexpr int N = 8192, NPTS = 4096, K = 2, C = 3;

    extern __shared__ float4 sxyz[];           // full N coords
    __shared__ unsigned rvu[2][32];
    __shared__ int      ri[2][32];
    __shared__ u64      mbox[2][4];            // [parity][source rank]
    __shared__ u64      mbar[2];               // mbarriers, count=4

    const int  t    = threadIdx.x;
    const int  lane = t & 31;
    const int  wid  = t >> 5;
    const uint32_t rank = my_cluster_rank();
    const int  b    = blockIdx.x >> 2;         // batch
    const int  base0 = (int)rank * 2048;       // this CTA's point range start

    const uint32_t mb_addr0 = smem_u32(&mbar[0]);
    const uint32_t mb_addr1 = smem_u32(&mbar[1]);

    if (t == 0) {
        asm volatile("mbarrier.init.shared.b64 [%0], %1;" :: "r"(mb_addr0), "r"(4u) : "memory");
        asm volatile("mbarrier.init.shared.b64 [%0], %1;" :: "r"(mb_addr1), "r"(4u) : "memory");
    }

    // load full coord copy
    const float* base = pts + (size_t)b * N * C;
    for (int i = t; i < N; i += 1024) {
        const float* r = base + (size_t)i * C;
        sxyz[i] = make_float4(r[0], r[1], r[2], 0.f);
    }
    __syncthreads();
    // all CTAs' mbarrier inits + smem visible before any cluster arrive
    asm volatile("barrier.cluster.arrive.aligned;" ::: "memory");
    asm volatile("barrier.cluster.wait.aligned;"   ::: "memory");

    if (rank == 0 && t == 0) idx_out[b * NPTS] = 0;

    // own points -> registers; initial distances to point 0 (R3-verbatim math)
    float x[K], y[K], z[K], d[K];
    float bv; int bi;
    {
        float4 q = sxyz[0];
        float px = q.x, py = q.y, pz = q.z;
#pragma unroll
        for (int k = 0; k < K; ++k) {
            int gi = base0 + t + k * 1024;
            float4 c = sxyz[gi];
            x[k] = c.x; y[k] = c.y; z[k] = c.z;
            float dx = x[k] - px, dy = y[k] - py, dz = z[k] - pz;
            d[k] = dx * dx + dy * dy + dz * dz;
        }
        bv = d[0]; bi = base0 + t;
#pragma unroll
        for (int k = 1; k < K; ++k) {
            int gi = base0 + t + k * 1024;
            if (d[k] > bv) { bv = d[k]; bi = gi; }
        }
    }

    uint32_t ph[2] = {0u, 0u};

    for (int it = 1; it < NPTS; ++it) {
        const int p = it & 1;

        // stage 1: warp reduce (max value bits, min global index on ties)
        unsigned ub = __float_as_uint(bv);
        unsigned m1 = __reduce_max_sync(0xffffffffu, ub);
        unsigned c1 = (ub == m1) ? (unsigned)bi : 0x7fffffffu;
        unsigned i1 = __reduce_min_sync(0xffffffffu, c1);
        if (lane == 0) { rvu[p][wid] = m1; ri[p][wid] = (int)i1; }
        __syncthreads();

        // stage 2: warps 0..3 reduce the 32 warp partials (they are senders)
        if (wid < 4) {
            unsigned vw = rvu[p][lane];
            int      iw = ri[p][lane];
            unsigned m2 = __reduce_max_sync(0xffffffffu, vw);
            unsigned c2 = (vw == m2) ? (unsigned)iw : 0x7fffffffu;
            int i2 = (int)__reduce_min_sync(0xffffffffu, c2);
            if (lane == 0) {
                u64 key = ((u64)m2 << 32) | (u64)(0xFFFFFFFFu - (unsigned)i2);
                // send this CTA's key to cluster CTA 'wid'
                uint32_t dst = mapa_rank(smem_u32(&mbox[p][rank]), (uint32_t)wid);
                asm volatile("st.shared::cluster.u64 [%0], %1;" :: "r"(dst), "l"(key) : "memory");
                uint32_t bar = mapa_rank(p ? mb_addr1 : mb_addr0, (uint32_t)wid);
                asm volatile("mbarrier.arrive.release.cluster.shared::cluster.b64 _, [%0];"
                             :: "r"(bar) : "memory");
            }
        }

        // wait for all 4 keys
        mbar_wait_cluster(p ? mb_addr1 : mb_addr0, ph[p]);
        ph[p] ^= 1u;

        u64 k0 = *(volatile u64*)&mbox[p][0];
        u64 k1 = *(volatile u64*)&mbox[p][1];
        u64 k2 = *(volatile u64*)&mbox[p][2];
        u64 k3 = *(volatile u64*)&mbox[p][3];
        u64 a  = k0 > k1 ? k0 : k1;
        u64 b2 = k2 > k3 ? k2 : k3;
        u64 g  = a > b2 ? a : b2;
        int bsel = (int)(0xFFFFFFFFu - (unsigned)(g & 0xFFFFFFFFull));

        if (rank == 0 && t == 0) idx_out[b * NPTS + it] = bsel;

        float4 q = sxyz[bsel];
        float px = q.x, py = q.y, pz = q.z;

        // update distances + fused thread-local argmax (R3-verbatim math)
        bv = -1.0f; bi = 0;
#pragma unroll
        for (int k = 0; k < K; ++k) {
            float dx = x[k] - px, dy = y[k] - py, dz = z[k] - pz;
            float nd = dx * dx + dy * dy + dz * dz;
            float dk = fminf(d[k], nd);
            d[k] = dk;
            int gi = base0 + t + k * 1024;
            if (dk > bv) { bv = dk; bi = gi; }
        }
    }

    // keep DSMEM targets alive until all peers finish
    asm volatile("barrier.cluster.arrive.aligned;" ::: "memory");
    asm volatile("barrier.cluster.wait.aligned;"   ::: "memory");
}

// ---------------------------------------------------------------------------
// Single-CTA FPS (levels 2-4), verbatim from R3.
// ---------------------------------------------------------------------------
template <int N, int K>
__global__ __launch_bounds__(1024, 1)
void fps_kernel(const float* __restrict__ pts, int C, int npoints,
                int* __restrict__ idx_out)
{
    extern __shared__ float4 sxyz[];
    __shared__ unsigned rvu[2][32];
    __shared__ int      ri[2][32];

    const int b    = blockIdx.x;
    const int t    = threadIdx.x;
    const int lane = t & 31;
    const int wid  = t >> 5;

    const float* base = pts + (size_t)b * N * C;

    float x[K], y[K], z[K], d[K];

#pragma unroll
    for (int k = 0; k < K; ++k) {
        int i = t + k * 1024;
        const float* r = base + (size_t)i * C;
        x[k] = r[0]; y[k] = r[1]; z[k] = r[2];
        sxyz[i] = make_float4(x[k], y[k], z[k], 0.f);
    }
    __syncthreads();

    if (t == 0) idx_out[b * npoints] = 0;

    {
        float4 q = sxyz[0];
        float px = q.x, py = q.y, pz = q.z;
#pragma unroll
        for (int k = 0; k < K; ++k) {
            float dx = x[k] - px, dy = y[k] - py, dz = z[k] - pz;
            d[k] = dx * dx + dy * dy + dz * dz;
        }
    }

    float bv = d[0];
    int   bi = t;
#pragma unroll
    for (int k = 1; k < K; ++k) {
        int gi = t + k * 1024;
        if (d[k] > bv) { bv = d[k]; bi = gi; }
    }

    for (int it = 1; it < npoints; ++it) {
        unsigned ub = __float_as_uint(bv);
        unsigned m1 = __reduce_max_sync(0xffffffffu, ub);
        unsigned c1 = (ub == m1) ? (unsigned)bi : 0x7fffffffu;
        unsigned i1 = __reduce_min_sync(0xffffffffu, c1);
        const int p = it & 1;
        if (lane == 0) { rvu[p][wid] = m1; ri[p][wid] = (int)i1; }
        __syncthreads();

        unsigned vw = rvu[p][lane];
        int      iw = ri[p][lane];
        unsigned m2 = __reduce_max_sync(0xffffffffu, vw);
        unsigned c2 = (vw == m2) ? (unsigned)iw : 0x7fffffffu;
        int bsel = (int)__reduce_min_sync(0xffffffffu, c2);
        if (t == 0) idx_out[b * npoints + it] = bsel;

        float4 q = sxyz[bsel];
        float px = q.x, py = q.y, pz = q.z;

        bv = -1.0f; bi = 0;
#pragma unroll
        for (int k = 0; k < K; ++k) {
            float dx = x[k] - px, dy = y[k] - py, dz = z[k] - pz;
            float nd = dx * dx + dy * dy + dz * dz;
            float dk = fminf(d[k], nd);
            d[k] = dk;
            int gi = t + k * 1024;
            if (dk > bv) { bv = dk; bi = gi; }
        }
    }
}

// ---------------------------------------------------------------------------
// Gather + pointwise 2-layer MLP + output assembly (unchanged).
// ---------------------------------------------------------------------------
template <int CPREV, int F, bool REPEAT>
__global__ __launch_bounds__(256)
void mlp_kernel(const float* __restrict__ in, const int* __restrict__ idx,
                const float* __restrict__ w1, const float* __restrict__ b1,
                const float* __restrict__ w2, const float* __restrict__ b2,
                float* __restrict__ out, int n_in, int npoints)
{
    constexpr int PPB = 256 / F;
    constexpr int CIN = REPEAT ? 2 * CPREV : CPREV;

    __shared__ float row[PPB][CPREV];
    __shared__ float hsm[PPB][F];

    const int t  = threadIdx.x;
    const int lp = t / F;
    const int g  = t % F;
    const int gp = blockIdx.x * PPB + lp;
    const int b  = gp / npoints;
    const int pt = gp % npoints;

    const int src = idx[b * npoints + pt];
    const float* r = in + ((size_t)b * n_in + src) * CPREV;
    if (g < CPREV) row[lp][g] = r[g];
    __syncthreads();

    float acc = b1[g];
#pragma unroll
    for (int c = 0; c < CIN; ++c)
        acc += row[lp][c % CPREV] * w1[c * F + g];
    hsm[lp][g] = fmaxf(acc, 0.0f);
    __syncthreads();

    float o = b2[g];
#pragma unroll
    for (int j = 0; j < F; ++j)
        o += hsm[lp][j] * w2[j * F + g];

    float* orow = out + ((size_t)b * npoints + pt) * F;
    orow[g] = (g < 3) ? row[lp][g] : o;
}

// ---------------------------------------------------------------------------
// Launch
// ---------------------------------------------------------------------------
extern "C" void kernel_launch(void* const* d_in, const int* in_sizes, int n_in_cnt,
                              void* d_out, int out_size)
{
    (void)in_sizes; (void)n_in_cnt; (void)out_size;

    const float* pts  = (const float*)d_in[0];
    const float* w1_1 = (const float*)d_in[1];
    const float* b1_1 = (const float*)d_in[2];
    const float* w2_1 = (const float*)d_in[3];
    const float* b2_1 = (const float*)d_in[4];
    const float* w1_2 = (const float*)d_in[5];
    const float* b1_2 = (const float*)d_in[6];
    const float* w2_2 = (const float*)d_in[7];
    const float* b2_2 = (const float*)d_in[8];
    const float* w1_3 = (const float*)d_in[9];
    const float* b1_3 = (const float*)d_in[10];
    const float* w2_3 = (const float*)d_in[11];
    const float* b2_3 = (const float*)d_in[12];
    const float* w1_4 = (const float*)d_in[13];
    const float* b1_4 = (const float*)d_in[14];
    const float* w2_4 = (const float*)d_in[15];
    const float* b2_4 = (const float*)d_in[16];

    float* out = (float*)d_out;
    const int B = 8;
    float* f1 = out;                        // [8,4096,16]
    float* f2 = out + 8 * 4096 * 16;        // [8,2048,32]
    float* f3 = f2 + 8 * 2048 * 32;         // [8,1024,64]
    float* f4 = f3 + 8 * 1024 * 64;         // [8, 512,128]

    static int* idx_buf = nullptr;
    if (!idx_buf) cudaGetSymbolAddress((void**)&idx_buf, g_fps_idx);

    static bool attr_done = false;
    if (!attr_done) {
        cudaFuncSetAttribute(fps1_cluster,
                             cudaFuncAttributeMaxDynamicSharedMemorySize, 8192 * 16);
        cudaFuncSetAttribute(fps_kernel<4096, 4>,
                             cudaFuncAttributeMaxDynamicSharedMemorySize, 4096 * 16);
        cudaFuncSetAttribute(fps_kernel<2048, 2>,
                             cudaFuncAttributeMaxDynamicSharedMemorySize, 2048 * 16);
        cudaFuncSetAttribute(fps_kernel<1024, 1>,
                             cudaFuncAttributeMaxDynamicSharedMemorySize, 1024 * 16);
        attr_done = true;
    }

    // ---- Level 1: 8192 -> 4096, 4-CTA cluster per batch ----
    fps1_cluster<<<B * 4, 1024, 8192 * 16>>>(pts, idx_buf);
    mlp_kernel<3, 16, true><<<(B * 4096) / 16, 256>>>(
        pts, idx_buf, w1_1, b1_1, w2_1, b2_1, f1, 8192, 4096);

    // ---- Level 2: 4096 -> 2048, C=16, F=32 ----
    fps_kernel<4096, 4><<<B, 1024, 4096 * 16>>>(f1, 16, 2048, idx_buf);
    mlp_kernel<16, 32, false><<<(B * 2048) / 8, 256>>>(
        f1, idx_buf, w1_2, b1_2, w2_2, b2_2, f2, 4096, 2048);

    // ---- Level 3: 2048 -> 1024, C=32, F=64 ----
    fps_kernel<2048, 2><<<B, 1024, 2048 * 16>>>(f2, 32, 1024, idx_buf);
    mlp_kernel<32, 64, false><<<(B * 1024) / 4, 256>>>(
        f2, idx_buf, w1_3, b1_3, w2_3, b2_3, f3, 2048, 1024);

    // ---- Level 4: 1024 -> 512, C=64, F=128 ----
    fps_kernel<1024, 1><<<B, 1024, 1024 * 16>>>(f3, 64, 512, idx_buf);
    mlp_kernel<64, 128, false><<<(B * 512) / 2, 256>>>(
        f3, idx_buf, w1_4, b1_4, w2_4, b2_4, f4, 1024, 512);
}

// round 5
// speedup vs baseline: 1.2445x; 1.2445x over previous
#include <cuda_runtime.h>
#include <cstdint>

// ---------------------------------------------------------------------------
// Scratch: FPS index buffer (max level-1 size: 8 batches x 4096 points)
// ---------------------------------------------------------------------------
__device__ int g_fps_idx[8 * 4096];

typedef unsigned long long u64;

// ---------------------------------------------------------------------------
// Cluster helpers
// ---------------------------------------------------------------------------
__device__ __forceinline__ uint32_t smem_u32(const void* p) {
    uint32_t a;
    asm("{ .reg .u64 t; cvta.to.shared.u64 t, %1; cvt.u32.u64 %0, t; }"
        : "=r"(a) : "l"(p));
    return a;
}
__device__ __forceinline__ uint32_t mapa_rank(uint32_t addr, uint32_t rank) {
    uint32_t o;
    asm("mapa.shared::cluster.u32 %0, %1, %2;" : "=r"(o) : "r"(addr), "r"(rank));
    return o;
}
__device__ __forceinline__ uint32_t my_cluster_rank() {
    uint32_t r; asm("mov.u32 %0, %%cluster_ctarank;" : "=r"(r)); return r;
}
__device__ __forceinline__ u64 lds_vol_u64(const u64* p) {
    u64 v;
    asm volatile("ld.volatile.shared.b64 %0, [%1];" : "=l"(v) : "r"(smem_u32(p)));
    return v;
}

// ---------------------------------------------------------------------------
// Level-1 FPS across a 4-CTA cluster, spin-mailbox exchange (no mbarrier).
// N=8192, npoints=4096. Each CTA owns 2048 points (K=2 register distances)
// and holds a FULL float4 copy of all 8192 coords, so only an 8-byte key
// crosses the fabric per iteration.
//
// Key layout: [63:32]=dist bits (>=0 so bit order == value order),
//             [31:12]=0xFFFFF - idx  (max key => min index among ties,
//                      exact jnp.argmax first-occurrence),
//             [11:0] =iteration tag (1..4095, all distinct) -> the word is
//                      self-validating; receivers spin on LOCAL smem.
// Parity-paired slots; safety: a CTA writes slot p for it+2 only after
// observing all peers' it+1 keys, which each peer sends after its barrier
// at it+1, i.e. after all its warps consumed slot p at it.
// Distance math verbatim from R3 (bit-matched to reference).
// ---------------------------------------------------------------------------
__global__ void __cluster_dims__(4, 1, 1) __launch_bounds__(1024, 1)
fps1_cluster(const float* __restrict__ pts, int* __restrict__ idx_out)
{
    constexpr int N = 8192, NPTS = 4096, K = 2, C = 3;

    extern __shared__ float4 sxyz[];           // full N coords
    __shared__ unsigned rvu[2][32];
    __shared__ int      ri[2][32];
    __shared__ u64      mbox[2][4];            // [parity][source rank]

    const int  t    = threadIdx.x;
    const int  lane = t & 31;
    const int  wid  = t >> 5;
    const uint32_t rank = my_cluster_rank();
    const int  b     = blockIdx.x >> 2;        // batch
    const int  base0 = (int)rank * 2048;       // this CTA's point range start

    if (t == 0) {
        mbox[0][0] = 0; mbox[0][1] = 0; mbox[0][2] = 0; mbox[0][3] = 0;
        mbox[1][0] = 0; mbox[1][1] = 0; mbox[1][2] = 0; mbox[1][3] = 0;
    }

    // load full coord copy
    const float* base = pts + (size_t)b * N * C;
    for (int i = t; i < N; i += 1024) {
        const float* r = base + (size_t)i * C;
        sxyz[i] = make_float4(r[0], r[1], r[2], 0.f);
    }
    __syncthreads();
    // all CTAs' mbox init visible before any peer may send (it=1)
    asm volatile("barrier.cluster.arrive.aligned;" ::: "memory");
    asm volatile("barrier.cluster.wait.aligned;"   ::: "memory");

    if (rank == 0 && t == 0) idx_out[b * NPTS] = 0;

    // own points -> registers; initial distances to point 0 (R3-verbatim math)
    float x[K], y[K], z[K], d[K];
    float bv; int bi;
    {
        float4 q = sxyz[0];
        float px = q.x, py = q.y, pz = q.z;
#pragma unroll
        for (int k = 0; k < K; ++k) {
            int gi = base0 + t + k * 1024;
            float4 c = sxyz[gi];
            x[k] = c.x; y[k] = c.y; z[k] = c.z;
            float dx = x[k] - px, dy = y[k] - py, dz = z[k] - pz;
            d[k] = dx * dx + dy * dy + dz * dz;
        }
        bv = d[0]; bi = base0 + t;
#pragma unroll
        for (int k = 1; k < K; ++k) {
            int gi = base0 + t + k * 1024;
            if (d[k] > bv) { bv = d[k]; bi = gi; }
        }
    }

    for (int it = 1; it < NPTS; ++it) {
        const int p = it & 1;
        const unsigned tag = (unsigned)it & 0xFFFu;

        // stage 1: warp reduce (max value bits, min global index on ties)
        unsigned ub = __float_as_uint(bv);
        unsigned m1 = __reduce_max_sync(0xffffffffu, ub);
        unsigned c1 = (ub == m1) ? (unsigned)bi : 0x7fffffffu;
        unsigned i1 = __reduce_min_sync(0xffffffffu, c1);
        if (lane == 0) { rvu[p][wid] = m1; ri[p][wid] = (int)i1; }
        __syncthreads();

        // stage 2: warps 0..3 reduce the 32 warp partials and send the CTA
        // key to cluster CTA 'wid' (4 parallel sends, one per dest)
        if (wid < 4) {
            unsigned vw = rvu[p][lane];
            int      iw = ri[p][lane];
            unsigned m2 = __reduce_max_sync(0xffffffffu, vw);
            unsigned c2 = (vw == m2) ? (unsigned)iw : 0x7fffffffu;
            int i2 = (int)__reduce_min_sync(0xffffffffu, c2);
            if (lane == 0) {
                u64 key = ((u64)m2 << 32)
                        | ((u64)((0xFFFFFu - (unsigned)i2) & 0xFFFFFu) << 12)
                        | (u64)tag;
                uint32_t dst = mapa_rank(smem_u32(&mbox[p][rank]), (uint32_t)wid);
                asm volatile("st.shared::cluster.u64 [%0], %1;"
                             :: "r"(dst), "l"(key) : "memory");
            }
        }

        // spin on local mailbox until all 4 tags match this iteration
        u64 k0, k1, k2, k3;
        do {
            k0 = lds_vol_u64(&mbox[p][0]);
            k1 = lds_vol_u64(&mbox[p][1]);
            k2 = lds_vol_u64(&mbox[p][2]);
            k3 = lds_vol_u64(&mbox[p][3]);
        } while (((unsigned)k0 & 0xFFFu) != tag || ((unsigned)k1 & 0xFFFu) != tag ||
                 ((unsigned)k2 & 0xFFFu) != tag || ((unsigned)k3 & 0xFFFu) != tag);

        u64 a  = k0 > k1 ? k0 : k1;
        u64 b2 = k2 > k3 ? k2 : k3;
        u64 g  = a > b2 ? a : b2;
        int bsel = (int)(0xFFFFFu - (unsigned)((g >> 12) & 0xFFFFFu));

        if (rank == 0 && t == 0) idx_out[b * NPTS + it] = bsel;

        float4 q = sxyz[bsel];
        float px = q.x, py = q.y, pz = q.z;

        // update distances + fused thread-local argmax (R3-verbatim math)
        bv = -1.0f; bi = 0;
#pragma unroll
        for (int k = 0; k < K; ++k) {
            float dx = x[k] - px, dy = y[k] - py, dz = z[k] - pz;
            float nd = dx * dx + dy * dy + dz * dz;
            float dk = fminf(d[k], nd);
            d[k] = dk;
            int gi = base0 + t + k * 1024;
            if (dk > bv) { bv = dk; bi = gi; }
        }
    }

    // keep DSMEM targets alive until all peers finish
    asm volatile("barrier.cluster.arrive.aligned;" ::: "memory");
    asm volatile("barrier.cluster.wait.aligned;"   ::: "memory");
}

// ---------------------------------------------------------------------------
// Single-CTA FPS (levels 2-4), verbatim from R3.
// ---------------------------------------------------------------------------
template <int N, int K>
__global__ __launch_bounds__(1024, 1)
void fps_kernel(const float* __restrict__ pts, int C, int npoints,
                int* __restrict__ idx_out)
{
    extern __shared__ float4 sxyz[];
    __shared__ unsigned rvu[2][32];
    __shared__ int      ri[2][32];

    const int b    = blockIdx.x;
    const int t    = threadIdx.x;
    const int lane = t & 31;
    const int wid  = t >> 5;

    const float* base = pts + (size_t)b * N * C;

    float x[K], y[K], z[K], d[K];

#pragma unroll
    for (int k = 0; k < K; ++k) {
        int i = t + k * 1024;
        const float* r = base + (size_t)i * C;
        x[k] = r[0]; y[k] = r[1]; z[k] = r[2];
        sxyz[i] = make_float4(x[k], y[k], z[k], 0.f);
    }
    __syncthreads();

    if (t == 0) idx_out[b * npoints] = 0;

    {
        float4 q = sxyz[0];
        float px = q.x, py = q.y, pz = q.z;
#pragma unroll
        for (int k = 0; k < K; ++k) {
            float dx = x[k] - px, dy = y[k] - py, dz = z[k] - pz;
            d[k] = dx * dx + dy * dy + dz * dz;
        }
    }

    float bv = d[0];
    int   bi = t;
#pragma unroll
    for (int k = 1; k < K; ++k) {
        int gi = t + k * 1024;
        if (d[k] > bv) { bv = d[k]; bi = gi; }
    }

    for (int it = 1; it < npoints; ++it) {
        unsigned ub = __float_as_uint(bv);
        unsigned m1 = __reduce_max_sync(0xffffffffu, ub);
        unsigned c1 = (ub == m1) ? (unsigned)bi : 0x7fffffffu;
        unsigned i1 = __reduce_min_sync(0xffffffffu, c1);
        const int p = it & 1;
        if (lane == 0) { rvu[p][wid] = m1; ri[p][wid] = (int)i1; }
        __syncthreads();

        unsigned vw = rvu[p][lane];
        int      iw = ri[p][lane];
        unsigned m2 = __reduce_max_sync(0xffffffffu, vw);
        unsigned c2 = (vw == m2) ? (unsigned)iw : 0x7fffffffu;
        int bsel = (int)__reduce_min_sync(0xffffffffu, c2);
        if (t == 0) idx_out[b * npoints + it] = bsel;

        float4 q = sxyz[bsel];
        float px = q.x, py = q.y, pz = q.z;

        bv = -1.0f; bi = 0;
#pragma unroll
        for (int k = 0; k < K; ++k) {
            float dx = x[k] - px, dy = y[k] - py, dz = z[k] - pz;
            float nd = dx * dx + dy * dy + dz * dz;
            float dk = fminf(d[k], nd);
            d[k] = dk;
            int gi = t + k * 1024;
            if (dk > bv) { bv = dk; bi = gi; }
        }
    }
}

// ---------------------------------------------------------------------------
// Gather + pointwise 2-layer MLP + output assembly (unchanged).
// ---------------------------------------------------------------------------
template <int CPREV, int F, bool REPEAT>
__global__ __launch_bounds__(256)
void mlp_kernel(const float* __restrict__ in, const int* __restrict__ idx,
                const float* __restrict__ w1, const float* __restrict__ b1,
                const float* __restrict__ w2, const float* __restrict__ b2,
                float* __restrict__ out, int n_in, int npoints)
{
    constexpr int PPB = 256 / F;
    constexpr int CIN = REPEAT ? 2 * CPREV : CPREV;

    __shared__ float row[PPB][CPREV];
    __shared__ float hsm[PPB][F];

    const int t  = threadIdx.x;
    const int lp = t / F;
    const int g  = t % F;
    const int gp = blockIdx.x * PPB + lp;
    const int b  = gp / npoints;
    const int pt = gp % npoints;

    const int src = idx[b * npoints + pt];
    const float* r = in + ((size_t)b * n_in + src) * CPREV;
    if (g < CPREV) row[lp][g] = r[g];
    __syncthreads();

    float acc = b1[g];
#pragma unroll
    for (int c = 0; c < CIN; ++c)
        acc += row[lp][c % CPREV] * w1[c * F + g];
    hsm[lp][g] = fmaxf(acc, 0.0f);
    __syncthreads();

    float o = b2[g];
#pragma unroll
    for (int j = 0; j < F; ++j)
        o += hsm[lp][j] * w2[j * F + g];

    float* orow = out + ((size_t)b * npoints + pt) * F;
    orow[g] = (g < 3) ? row[lp][g] : o;
}

// ---------------------------------------------------------------------------
// Launch
// ---------------------------------------------------------------------------
extern "C" void kernel_launch(void* const* d_in, const int* in_sizes, int n_in_cnt,
                              void* d_out, int out_size)
{
    (void)in_sizes; (void)n_in_cnt; (void)out_size;

    const float* pts  = (const float*)d_in[0];
    const float* w1_1 = (const float*)d_in[1];
    const float* b1_1 = (const float*)d_in[2];
    const float* w2_1 = (const float*)d_in[3];
    const float* b2_1 = (const float*)d_in[4];
    const float* w1_2 = (const float*)d_in[5];
    const float* b1_2 = (const float*)d_in[6];
    const float* w2_2 = (const float*)d_in[7];
    const float* b2_2 = (const float*)d_in[8];
    const float* w1_3 = (const float*)d_in[9];
    const float* b1_3 = (const float*)d_in[10];
    const float* w2_3 = (const float*)d_in[11];
    const float* b2_3 = (const float*)d_in[12];
    const float* w1_4 = (const float*)d_in[13];
    const float* b1_4 = (const float*)d_in[14];
    const float* w2_4 = (const float*)d_in[15];
    const float* b2_4 = (const float*)d_in[16];

    float* out = (float*)d_out;
    const int B = 8;
    float* f1 = out;                        // [8,4096,16]
    float* f2 = out + 8 * 4096 * 16;        // [8,2048,32]
    float* f3 = f2 + 8 * 2048 * 32;         // [8,1024,64]
    float* f4 = f3 + 8 * 1024 * 64;         // [8, 512,128]

    static int* idx_buf = nullptr;
    if (!idx_buf) cudaGetSymbolAddress((void**)&idx_buf, g_fps_idx);

    static bool attr_done = false;
    if (!attr_done) {
        cudaFuncSetAttribute(fps1_cluster,
                             cudaFuncAttributeMaxDynamicSharedMemorySize, 8192 * 16);
        cudaFuncSetAttribute(fps_kernel<4096, 4>,
                             cudaFuncAttributeMaxDynamicSharedMemorySize, 4096 * 16);
        cudaFuncSetAttribute(fps_kernel<2048, 2>,
                             cudaFuncAttributeMaxDynamicSharedMemorySize, 2048 * 16);
        cudaFuncSetAttribute(fps_kernel<1024, 1>,
                             cudaFuncAttributeMaxDynamicSharedMemorySize, 1024 * 16);
        attr_done = true;
    }

    // ---- Level 1: 8192 -> 4096, 4-CTA cluster per batch ----
    fps1_cluster<<<B * 4, 1024, 8192 * 16>>>(pts, idx_buf);
    mlp_kernel<3, 16, true><<<(B * 4096) / 16, 256>>>(
        pts, idx_buf, w1_1, b1_1, w2_1, b2_1, f1, 8192, 4096);

    // ---- Level 2: 4096 -> 2048, C=16, F=32 ----
    fps_kernel<4096, 4><<<B, 1024, 4096 * 16>>>(f1, 16, 2048, idx_buf);
    mlp_kernel<16, 32, false><<<(B * 2048) / 8, 256>>>(
        f1, idx_buf, w1_2, b1_2, w2_2, b2_2, f2, 4096, 2048);

    // ---- Level 3: 2048 -> 1024, C=32, F=64 ----
    fps_kernel<2048, 2><<<B, 1024, 2048 * 16>>>(f2, 32, 1024, idx_buf);
    mlp_kernel<32, 64, false><<<(B * 1024) / 4, 256>>>(
        f2, idx_buf, w1_3, b1_3, w2_3, b2_3, f3, 2048, 1024);

    // ---- Level 4: 1024 -> 512, C=64, F=128 ----
    fps_kernel<1024, 1><<<B, 1024, 1024 * 16>>>(f3, 64, 512, idx_buf);
    mlp_kernel<64, 128, false><<<(B * 512) / 2, 256>>>(
        f3, idx_buf, w1_4, b1_4, w2_4, b2_4, f4, 1024, 512);
}

// round 6
// speedup vs baseline: 1.3624x; 1.0948x over previous
#include <cuda_runtime.h>
#include <cstdint>

// ---------------------------------------------------------------------------
// Scratch: FPS index buffer (max level-1 size: 8 batches x 4096 points)
// ---------------------------------------------------------------------------
__device__ int g_fps_idx[8 * 4096];

typedef unsigned long long u64;

// ---------------------------------------------------------------------------
// Packed f32x2 helpers — ADD ONLY (per-lane IEEE rn; bisect showed the R2
// failure lived in the packed mul/fma chain, so those stay scalar).
// ---------------------------------------------------------------------------
__device__ __forceinline__ u64 pack2(float a, float b) {
    u64 r; asm("mov.b64 %0, {%1, %2};" : "=l"(r) : "f"(a), "f"(b)); return r;
}
__device__ __forceinline__ void unpack2(u64 v, float& a, float& b) {
    asm("mov.b64 {%0, %1}, %2;" : "=f"(a), "=f"(b) : "l"(v));
}
__device__ __forceinline__ u64 add2(u64 a, u64 b) {
    u64 r; asm("add.rn.f32x2 %0, %1, %2;" : "=l"(r) : "l"(a), "l"(b)); return r;
}

// ---------------------------------------------------------------------------
// Single-CTA FPS (all levels). One block (1024 threads) per batch.
// Structure identical to the R3 kernel (redux argmax, one __syncthreads per
// iteration, float4 SMEM fetch of the winner). The ONLY change vs R3: for
// K>=2 the three coordinate subtractions are done pairwise with
// add.rn.f32x2 (x + (-px)); negation is exact and packed add is per-lane
// IEEE rn, so bits match scalar FADD. The squared-sum keeps the VERBATIM
// R3 expression (dx*dx + dy*dy + dz*dz -> FMUL+FFMA+FFMA contraction).
// ---------------------------------------------------------------------------
template <int N, int K>
__global__ __launch_bounds__(1024, 1)
void fps_kernel(const float* __restrict__ pts, int C, int npoints,
                int* __restrict__ idx_out)
{
    extern __shared__ float4 sxyz[];
    __shared__ unsigned rvu[2][32];
    __shared__ int      ri[2][32];

    const int b    = blockIdx.x;
    const int t    = threadIdx.x;
    const int lane = t & 31;
    const int wid  = t >> 5;

    const float* base = pts + (size_t)b * N * C;

    float d[K];
    constexpr int KP = (K >= 2) ? K / 2 : 1;
    u64 xp[KP], yp[KP], zp[KP];               // packed coords (K>=2)
    float xs = 0.f, ys = 0.f, zs = 0.f;       // scalar coords (K==1)

    // load coords + SMEM float4 copy + initial distances to point 0
    {
        float x[K], y[K], z[K];
#pragma unroll
        for (int k = 0; k < K; ++k) {
            int i = t + k * 1024;
            const float* r = base + (size_t)i * C;
            x[k] = r[0]; y[k] = r[1]; z[k] = r[2];
            sxyz[i] = make_float4(x[k], y[k], z[k], 0.f);
        }
        __syncthreads();

        float4 q = sxyz[0];
        float px = q.x, py = q.y, pz = q.z;
#pragma unroll
        for (int k = 0; k < K; ++k) {
            float dx = x[k] - px, dy = y[k] - py, dz = z[k] - pz;
            d[k] = dx * dx + dy * dy + dz * dz;
        }

        if constexpr (K >= 2) {
#pragma unroll
            for (int k2 = 0; k2 < KP; ++k2) {
                xp[k2] = pack2(x[2 * k2], x[2 * k2 + 1]);
                yp[k2] = pack2(y[2 * k2], y[2 * k2 + 1]);
                zp[k2] = pack2(z[2 * k2], z[2 * k2 + 1]);
            }
        } else {
            xs = x[0]; ys = y[0]; zs = z[0];
        }
    }

    if (t == 0) idx_out[b * npoints] = 0;

    // thread-local argmax of initial distances (strict > keeps lowest index)
    float bv = d[0];
    int   bi = t;
#pragma unroll
    for (int k = 1; k < K; ++k) {
        int gi = t + k * 1024;
        if (d[k] > bv) { bv = d[k]; bi = gi; }
    }

    for (int it = 1; it < npoints; ++it) {
        // stage 1: warp reduce via redux (max value bits, min index on ties)
        unsigned ub = __float_as_uint(bv);
        unsigned m1 = __reduce_max_sync(0xffffffffu, ub);
        unsigned c1 = (ub == m1) ? (unsigned)bi : 0x7fffffffu;
        unsigned i1 = __reduce_min_sync(0xffffffffu, c1);
        const int p = it & 1;
        if (lane == 0) { rvu[p][wid] = m1; ri[p][wid] = (int)i1; }
        __syncthreads();

        // stage 2: every warp reduces the 32 warp results redundantly
        unsigned vw = rvu[p][lane];
        int      iw = ri[p][lane];
        unsigned m2 = __reduce_max_sync(0xffffffffu, vw);
        unsigned c2 = (vw == m2) ? (unsigned)iw : 0x7fffffffu;
        int bsel = (int)__reduce_min_sync(0xffffffffu, c2);
        if (t == 0) idx_out[b * npoints + it] = bsel;

        float4 q = sxyz[bsel];                // LDS.128 broadcast
        float px = q.x, py = q.y, pz = q.z;

        // update distances + fused thread-local argmax
        bv = -1.0f; bi = 0;
        if constexpr (K >= 2) {
            const u64 nxp = pack2(-px, -px);  // negation exact
            const u64 nyp = pack2(-py, -py);
            const u64 nzp = pack2(-pz, -pz);
#pragma unroll
            for (int k2 = 0; k2 < KP; ++k2) {
                float dx0, dx1, dy0, dy1, dz0, dz1;
                unpack2(add2(xp[k2], nxp), dx0, dx1);   // == x - px, bitwise
                unpack2(add2(yp[k2], nyp), dy0, dy1);
                unpack2(add2(zp[k2], nzp), dz0, dz1);
                // VERBATIM R3 squared-sum (FMUL+FFMA+FFMA contraction)
                float nd0 = dx0 * dx0 + dy0 * dy0 + dz0 * dz0;
                float nd1 = dx1 * dx1 + dy1 * dy1 + dz1 * dz1;
                float dk0 = fminf(d[2 * k2],     nd0);
                float dk1 = fminf(d[2 * k2 + 1], nd1);
                d[2 * k2]     = dk0;
                d[2 * k2 + 1] = dk1;
                int g0 = t + (2 * k2) * 1024;
                int g1 = g0 + 1024;
                if (dk0 > bv) { bv = dk0; bi = g0; }
                if (dk1 > bv) { bv = dk1; bi = g1; }
            }
        } else {
            float dx = xs - px, dy = ys - py, dz = zs - pz;
            float nd = dx * dx + dy * dy + dz * dz;
            float dk = fminf(d[0], nd);
            d[0] = dk; bv = dk; bi = t;
        }
    }
}

// ---------------------------------------------------------------------------
// Gather + pointwise 2-layer MLP + output assembly (unchanged).
// ---------------------------------------------------------------------------
template <int CPREV, int F, bool REPEAT>
__global__ __launch_bounds__(256)
void mlp_kernel(const float* __restrict__ in, const int* __restrict__ idx,
                const float* __restrict__ w1, const float* __restrict__ b1,
                const float* __restrict__ w2, const float* __restrict__ b2,
                float* __restrict__ out, int n_in, int npoints)
{
    constexpr int PPB = 256 / F;
    constexpr int CIN = REPEAT ? 2 * CPREV : CPREV;

    __shared__ float row[PPB][CPREV];
    __shared__ float hsm[PPB][F];

    const int t  = threadIdx.x;
    const int lp = t / F;
    const int g  = t % F;
    const int gp = blockIdx.x * PPB + lp;
    const int b  = gp / npoints;
    const int pt = gp % npoints;

    const int src = idx[b * npoints + pt];
    const float* r = in + ((size_t)b * n_in + src) * CPREV;
    if (g < CPREV) row[lp][g] = r[g];
    __syncthreads();

    float acc = b1[g];
#pragma unroll
    for (int c = 0; c < CIN; ++c)
        acc += row[lp][c % CPREV] * w1[c * F + g];
    hsm[lp][g] = fmaxf(acc, 0.0f);
    __syncthreads();

    float o = b2[g];
#pragma unroll
    for (int j = 0; j < F; ++j)
        o += hsm[lp][j] * w2[j * F + g];

    float* orow = out + ((size_t)b * npoints + pt) * F;
    orow[g] = (g < 3) ? row[lp][g] : o;
}

// ---------------------------------------------------------------------------
// Launch
// ---------------------------------------------------------------------------
extern "C" void kernel_launch(void* const* d_in, const int* in_sizes, int n_in_cnt,
                              void* d_out, int out_size)
{
    (void)in_sizes; (void)n_in_cnt; (void)out_size;

    const float* pts  = (const float*)d_in[0];
    const float* w1_1 = (const float*)d_in[1];
    const float* b1_1 = (const float*)d_in[2];
    const float* w2_1 = (const float*)d_in[3];
    const float* b2_1 = (const float*)d_in[4];
    const float* w1_2 = (const float*)d_in[5];
    const float* b1_2 = (const float*)d_in[6];
    const float* w2_2 = (const float*)d_in[7];
    const float* b2_2 = (const float*)d_in[8];
    const float* w1_3 = (const float*)d_in[9];
    const float* b1_3 = (const float*)d_in[10];
    const float* w2_3 = (const float*)d_in[11];
    const float* b2_3 = (const float*)d_in[12];
    const float* w1_4 = (const float*)d_in[13];
    const float* b1_4 = (const float*)d_in[14];
    const float* w2_4 = (const float*)d_in[15];
    const float* b2_4 = (const float*)d_in[16];

    float* out = (float*)d_out;
    const int B = 8;
    float* f1 = out;                        // [8,4096,16]
    float* f2 = out + 8 * 4096 * 16;        // [8,2048,32]
    float* f3 = f2 + 8 * 2048 * 32;         // [8,1024,64]
    float* f4 = f3 + 8 * 1024 * 64;         // [8, 512,128]

    static int* idx_buf = nullptr;
    if (!idx_buf) cudaGetSymbolAddress((void**)&idx_buf, g_fps_idx);

    static bool attr_done = false;
    if (!attr_done) {
        cudaFuncSetAttribute(fps_kernel<8192, 8>,
                             cudaFuncAttributeMaxDynamicSharedMemorySize, 8192 * 16);
        cudaFuncSetAttribute(fps_kernel<4096, 4>,
                             cudaFuncAttributeMaxDynamicSharedMemorySize, 4096 * 16);
        cudaFuncSetAttribute(fps_kernel<2048, 2>,
                             cudaFuncAttributeMaxDynamicSharedMemorySize, 2048 * 16);
        cudaFuncSetAttribute(fps_kernel<1024, 1>,
                             cudaFuncAttributeMaxDynamicSharedMemorySize, 1024 * 16);
        attr_done = true;
    }

    // ---- Level 1: 8192 -> 4096, C=3 (repeat to 6), F=16 ----
    fps_kernel<8192, 8><<<B, 1024, 8192 * 16>>>(pts, 3, 4096, idx_buf);
    mlp_kernel<3, 16, true><<<(B * 4096) / 16, 256>>>(
        pts, idx_buf, w1_1, b1_1, w2_1, b2_1, f1, 8192, 4096);

    // ---- Level 2: 4096 -> 2048, C=16, F=32 ----
    fps_kernel<4096, 4><<<B, 1024, 4096 * 16>>>(f1, 16, 2048, idx_buf);
    mlp_kernel<16, 32, false><<<(B * 2048) / 8, 256>>>(
        f1, idx_buf, w1_2, b1_2, w2_2, b2_2, f2, 4096, 2048);

    // ---- Level 3: 2048 -> 1024, C=32, F=64 ----
    fps_kernel<2048, 2><<<B, 1024, 2048 * 16>>>(f2, 32, 1024, idx_buf);
    mlp_kernel<32, 64, false><<<(B * 1024) / 4, 256>>>(
        f2, idx_buf, w1_3, b1_3, w2_3, b2_3, f3, 2048, 1024);

    // ---- Level 4: 1024 -> 512, C=64, F=128 ----
    fps_kernel<1024, 1><<<B, 1024, 1024 * 16>>>(f3, 64, 512, idx_buf);
    mlp_kernel<64, 128, false><<<(B * 512) / 2, 256>>>(
        f3, idx_buf, w1_4, b1_4, w2_4, b2_4, f4, 1024, 512);
}